// round 7
// baseline (speedup 1.0000x reference)
#include <cuda_runtime.h>
#include <cuda_bf16.h>
#include <cstdint>

// ---------------------------------------------------------------------------
// FastAttention (Performer / FAVOR+) — TF32 warp-MMA, fused k-side pipeline
//   b=4, h=8 (BH=32), n=4096, d=64, m=266, e=64
// Key identity: k-side stabilizer/ratio scale C=ratio*e^-s cancels in
//   out = (qp@context)/(qp·kmean). Fused kernel accumulates UNSTABBED
//   E=exp(d-diag): g_context=ΣEv, g_kmean=ΣE, g_vsum=Σv, s=max(d).
//   k3 applies EPS'=EPS*e^s:  CTX=ΣEv+EPS'·Σv,  KM=ΣE+L·EPS'.
// Bank rule: g(lane>>2)-indexed rows -> stride 68; tg-indexed -> stride 72.
// ---------------------------------------------------------------------------

#define BH    32
#define NSEQ  4096
#define DDIM  64
#define MDIM  266
#define EDIM  64
#define MPAD  272

constexpr float DN_F    = 0.35355339059327373f;  // 64^-0.25
constexpr float DIAG_C  = 0.0625f;               // 0.5 * DN^2
constexpr float RATIO_F = 0.06131393316f;        // 266^-0.5
constexpr float EPS_F   = 1e-4f;

// ------------------------------ scratch ------------------------------------
__device__ __align__(16) float g_context[BH * MDIM * EDIM];  // ΣE·v
__device__ __align__(16) float g_kmean[BH * MDIM];           // ΣE
__device__ __align__(16) float g_vsum[BH * EDIM];            // Σv
__device__ unsigned            g_kmax_u;

__device__ __forceinline__ unsigned fenc(float f) {
    unsigned u = __float_as_uint(f);
    return (u & 0x80000000u) ? ~u : (u | 0x80000000u);
}
__device__ __forceinline__ float fdec(unsigned k) {
    return (k & 0x80000000u) ? __uint_as_float(k ^ 0x80000000u)
                             : __uint_as_float(~k);
}
__device__ __forceinline__ unsigned f2tf(float x) {
    unsigned r;
    asm("cvt.rna.tf32.f32 %0, %1;" : "=r"(r) : "f"(x));
    return r;
}
__device__ __forceinline__ void mma8(float* c, unsigned a0, unsigned a1,
                                     unsigned a2, unsigned a3,
                                     unsigned b0, unsigned b1) {
    asm volatile(
        "mma.sync.aligned.m16n8k8.row.col.f32.tf32.tf32.f32 "
        "{%0,%1,%2,%3}, {%4,%5,%6,%7}, {%8,%9}, {%0,%1,%2,%3};"
        : "+f"(c[0]), "+f"(c[1]), "+f"(c[2]), "+f"(c[3])
        : "r"(a0), "r"(a1), "r"(a2), "r"(a3), "r"(b0), "r"(b1));
}

// 64x64 fp32 -> tf32 tile at row stride S (words). 256 threads.
__device__ __forceinline__ void load_tileS(unsigned* dst, int S,
                                           const float* __restrict__ src,
                                           int valid, int tid) {
#pragma unroll
    for (int t = 0; t < 4; t++) {
        int idx = tid + (t << 8);
        int r = idx >> 4, c4 = (idx & 15) << 2;
        float4 v = (r < valid) ? *(const float4*)(src + (size_t)r * 64 + c4)
                               : make_float4(0.f, 0.f, 0.f, 0.f);
        uint4 u;
        u.x = f2tf(v.x); u.y = f2tf(v.y); u.z = f2tf(v.z); u.w = f2tf(v.w);
        *(uint4*)&dst[r * S + c4] = u;
    }
}
// same (64 valid rows) + DIAG_C * sum(row^2) of ORIGINAL fp32 -> diag_out[r]
__device__ __forceinline__ void load_tile_diagS(unsigned* dst, int S,
                                                const float* __restrict__ src,
                                                int tid, float* diag_out) {
#pragma unroll
    for (int t = 0; t < 4; t++) {
        int idx = tid + (t << 8);
        int r = idx >> 4, c4 = (idx & 15) << 2;
        float4 v = *(const float4*)(src + (size_t)r * 64 + c4);
        float s = v.x * v.x + v.y * v.y + v.z * v.z + v.w * v.w;
        s += __shfl_xor_sync(0xffffffffu, s, 1);
        s += __shfl_xor_sync(0xffffffffu, s, 2);
        s += __shfl_xor_sync(0xffffffffu, s, 4);
        s += __shfl_xor_sync(0xffffffffu, s, 8);
        uint4 u;
        u.x = f2tf(v.x); u.y = f2tf(v.y); u.z = f2tf(v.z); u.w = f2tf(v.w);
        *(uint4*)&dst[r * S + c4] = u;
        if ((tid & 15) == 0) diag_out[r] = DIAG_C * s;
    }
}

// ------------------------------ k0: init -----------------------------------
__global__ void k0_init() {
    int i = blockIdx.x * blockDim.x + threadIdx.x;
    int stride = gridDim.x * blockDim.x;
    if (i == 0) g_kmax_u = 0u;
    for (int t = i; t < BH * MDIM * EDIM; t += stride) g_context[t] = 0.f;
    for (int t = i; t < BH * MDIM; t += stride)        g_kmean[t] = 0.f;
    for (int t = i; t < BH * EDIM; t += stride)        g_vsum[t] = 0.f;
}

// ------------------------------ kA: fused k-side ---------------------------
// grid (5 m-blocks, BH, 4 z-splits). Per chunk: mma1 d=k@(DN P)^T -> exp in
// regs -> smem -> mma2 context += kp^T @ v.
constexpr int KA_PS_W = 64 * 68;
constexpr int KA_KS_W = 64 * 68;
constexpr int KA_KP_W = 64 * 72;
constexpr int KA_V_W  = 64 * 72;
constexpr int KA_WORDS = KA_PS_W + KA_KS_W + KA_KP_W + KA_V_W + 64 + 64 + 8;
constexpr int KA_BYTES = KA_WORDS * 4;   // 72,224 B

__global__ __launch_bounds__(256, 2) void kA_context(
        const float* __restrict__ K, const float* __restrict__ V,
        const float* __restrict__ Pm) {
    extern __shared__ __align__(16) unsigned sa[];
    unsigned* Ps  = sa;                        // [64][68] DN*P tf32
    unsigned* Ks  = sa + KA_PS_W;              // [64][68]
    unsigned* KPu = sa + KA_PS_W + KA_KS_W;    // [64][72] exp values
    unsigned* Vu  = KPu + KA_KP_W;             // [64][72]
    float* diag = (float*)(Vu + KA_V_W);
    float* msum = diag + 64;
    float* red  = msum + 64;

    int tid = threadIdx.x, lane = tid & 31, warp = tid >> 5;
    int g = lane >> 2, tg = lane & 3;
    int m0 = blockIdx.x << 6, bh = blockIdx.y, cz = blockIdx.z << 4;

    // mma1 (64n x 64m): 2 n-slabs x 4 m-slabs -> 32x16 per warp
    int nr1 = (warp & 1) << 5;
    int cb1 = (warp >> 1) << 4;
    // mma2 (64m x 64e): 2 m-slabs x 4 e-slabs -> 32x16 per warp
    int mh = (warp & 1) << 5;
    int eb = (warp >> 1) << 4;

    // P tile loaded once, pre-scaled by DN
    {
        const float* pb = Pm + (size_t)m0 * DDIM;
        int valid = MDIM - m0;
#pragma unroll
        for (int t = 0; t < 4; t++) {
            int idx = tid + (t << 8);
            int r = idx >> 4, c4 = (idx & 15) << 2;
            float4 v = (r < valid) ? *(const float4*)(pb + (size_t)r * 64 + c4)
                                   : make_float4(0.f, 0.f, 0.f, 0.f);
            uint4 u;
            u.x = f2tf(DN_F * v.x); u.y = f2tf(DN_F * v.y);
            u.z = f2tf(DN_F * v.z); u.w = f2tf(DN_F * v.w);
            *(uint4*)&Ps[r * 68 + c4] = u;
        }
    }
    if (tid < 64) msum[tid] = 0.f;

    float lmax = -3.0e38f;
    float msl[2][2] = {{0.f, 0.f}, {0.f, 0.f}};
    float vs_loc = 0.f;
    float acc2[2][2][4];
#pragma unroll
    for (int i = 0; i < 2; i++)
#pragma unroll
        for (int j = 0; j < 2; j++)
#pragma unroll
            for (int q = 0; q < 4; q++) acc2[i][j][q] = 0.f;

    for (int nc = 0; nc < 16; nc++) {
        int n0 = (cz + nc) << 6;
        __syncthreads();   // S1: prev mma1/mma2 done with Ks/KPu/Vu

        load_tile_diagS(Ks, 68, K + ((size_t)bh * NSEQ + n0) * DDIM, tid, diag);
        const float* vb = V + ((size_t)bh * NSEQ + n0) * EDIM;
#pragma unroll
        for (int t = 0; t < 4; t++) {
            int idx = tid + (t << 8);
            int r = idx >> 4, c4 = (idx & 15) << 2;
            float4 v = *(const float4*)(vb + (size_t)r * 64 + c4);
            uint4 u;
            u.x = f2tf(v.x); u.y = f2tf(v.y); u.z = f2tf(v.z); u.w = f2tf(v.w);
            *(uint4*)&Vu[r * 72 + c4] = u;
        }
        __syncthreads();   // S2: Ks/diag/Vu ready

        if (m0 == 0) {     // vsum only needed once per (bh,z)
            int col = tid & 63, rr = tid >> 6;
            float s = 0.f;
#pragma unroll
            for (int t = 0; t < 16; t++)
                s += __uint_as_float(Vu[(rr + (t << 2)) * 72 + col]);
            vs_loc += s;
        }

        // ---- mma1: d = k @ (DN P)^T ----
        float c1[2][2][4];
#pragma unroll
        for (int i = 0; i < 2; i++)
#pragma unroll
            for (int j = 0; j < 2; j++)
#pragma unroll
                for (int q = 0; q < 4; q++) c1[i][j][q] = 0.f;

#pragma unroll
        for (int ks = 0; ks < 8; ks++) {
            int k0 = ks << 3;
            unsigned a[2][4], b[2][2];
#pragma unroll
            for (int i = 0; i < 2; i++) {
                int r0 = nr1 + (i << 4);
                a[i][0] = Ks[(r0 + g) * 68 + k0 + tg];
                a[i][1] = Ks[(r0 + g + 8) * 68 + k0 + tg];
                a[i][2] = Ks[(r0 + g) * 68 + k0 + tg + 4];
                a[i][3] = Ks[(r0 + g + 8) * 68 + k0 + tg + 4];
            }
#pragma unroll
            for (int j = 0; j < 2; j++) {
                int mcol = cb1 + (j << 3) + g;
                b[j][0] = Ps[mcol * 68 + k0 + tg];
                b[j][1] = Ps[mcol * 68 + k0 + tg + 4];
            }
#pragma unroll
            for (int i = 0; i < 2; i++)
#pragma unroll
                for (int j = 0; j < 2; j++)
                    mma8(c1[i][j], a[i][0], a[i][1], a[i][2], a[i][3],
                         b[j][0], b[j][1]);
        }

        // ---- exp in registers -> KPu ----
#pragma unroll
        for (int i = 0; i < 2; i++) {
            int r = nr1 + (i << 4) + g;
            float dg0 = diag[r], dg1 = diag[r + 8];
#pragma unroll
            for (int j = 0; j < 2; j++) {
                int m = cb1 + (j << 3) + (tg << 1);
                bool mv = (m0 + m) < MDIM;
                float d0 = c1[i][j][0], d1 = c1[i][j][1];
                float d2 = c1[i][j][2], d3 = c1[i][j][3];
                lmax = fmaxf(lmax, fmaxf(fmaxf(d0, d1), fmaxf(d2, d3)));
                float e0 = 0.f, e1 = 0.f, e2 = 0.f, e3 = 0.f;
                if (mv) {
                    e0 = __expf(d0 - dg0); e1 = __expf(d1 - dg0);
                    e2 = __expf(d2 - dg1); e3 = __expf(d3 - dg1);
                }
                KPu[r * 72 + m]           = f2tf(e0);
                KPu[r * 72 + m + 1]       = f2tf(e1);
                KPu[(r + 8) * 72 + m]     = f2tf(e2);
                KPu[(r + 8) * 72 + m + 1] = f2tf(e3);
                msl[j][0] += e0 + e2;
                msl[j][1] += e1 + e3;
            }
        }
        __syncthreads();   // S3: KPu ready

        // ---- mma2: context += kp^T @ v ----
#pragma unroll
        for (int ks = 0; ks < 8; ks++) {
            int k0 = ks << 3;
            unsigned a[2][4], b[2][2];
#pragma unroll
            for (int i = 0; i < 2; i++) {
                int mr = mh + (i << 4);
                a[i][0] = KPu[(k0 + tg) * 72 + mr + g];
                a[i][1] = KPu[(k0 + tg) * 72 + mr + g + 8];
                a[i][2] = KPu[(k0 + tg + 4) * 72 + mr + g];
                a[i][3] = KPu[(k0 + tg + 4) * 72 + mr + g + 8];
            }
#pragma unroll
            for (int j = 0; j < 2; j++) {
                int ec = eb + (j << 3) + g;
                b[j][0] = Vu[(k0 + tg) * 72 + ec];
                b[j][1] = Vu[(k0 + tg + 4) * 72 + ec];
            }
#pragma unroll
            for (int i = 0; i < 2; i++)
#pragma unroll
                for (int j = 0; j < 2; j++)
                    mma8(acc2[i][j], a[i][0], a[i][1], a[i][2], a[i][3],
                         b[j][0], b[j][1]);
        }
    }

    // ---- epilogue: kmean, stab max, vsum, context ----
#pragma unroll
    for (int j = 0; j < 2; j++)
#pragma unroll
        for (int c = 0; c < 2; c++) {
            float v = msl[j][c];
            v += __shfl_xor_sync(0xffffffffu, v, 4);
            v += __shfl_xor_sync(0xffffffffu, v, 8);
            v += __shfl_xor_sync(0xffffffffu, v, 16);
            if (g == 0) atomicAdd(&msum[cb1 + (j << 3) + (tg << 1) + c], v);
        }
#pragma unroll
    for (int o = 16; o > 0; o >>= 1)
        lmax = fmaxf(lmax, __shfl_xor_sync(0xffffffffu, lmax, o));
    if (lane == 0) red[warp] = lmax;
    __syncthreads();
    if (tid < 64 && m0 + tid < MDIM)
        atomicAdd(&g_kmean[bh * MDIM + m0 + tid], msum[tid]);
    if (tid < 8) {
        lmax = red[tid];
        lmax = fmaxf(lmax, __shfl_xor_sync(0xffu, lmax, 1));
        lmax = fmaxf(lmax, __shfl_xor_sync(0xffu, lmax, 2));
        lmax = fmaxf(lmax, __shfl_xor_sync(0xffu, lmax, 4));
        if (tid == 0) atomicMax(&g_kmax_u, fenc(lmax));
    }
    if (m0 == 0) atomicAdd(&g_vsum[bh * 64 + (tid & 63)], vs_loc);

#pragma unroll
    for (int i = 0; i < 2; i++) {
        int mbase = m0 + mh + (i << 4);
#pragma unroll
        for (int j = 0; j < 2; j++) {
            int e = eb + (j << 3) + (tg << 1);
            int m = mbase + g;
            if (m < MDIM) {
                float* p = g_context + ((size_t)bh * MDIM + m) * EDIM + e;
                atomicAdd(p + 0, acc2[i][j][0]);
                atomicAdd(p + 1, acc2[i][j][1]);
            }
            if (m + 8 < MDIM) {
                float* p = g_context + ((size_t)bh * MDIM + m + 8) * EDIM + e;
                atomicAdd(p + 0, acc2[i][j][2]);
                atomicAdd(p + 1, acc2[i][j][3]);
            }
        }
    }
}

// ------------------------------ k3: output ---------------------------------
constexpr int SM3_QP_W = MPAD * 72;                // 19584: qp[272][72]
constexpr int SM3_TQ_W = 64 * 68;                  // 4352: Q tile / obuf alias
constexpr int SM3_TP_W = 64 * 72;                  // 4608: P(68)/context(72)/km
constexpr int SM3_WMAX = 4 * 64;                   // 256
constexpr int SM3_WORDS = SM3_QP_W + SM3_TQ_W + SM3_TP_W + SM3_WMAX
                          + 64 + 64 + 64;
constexpr int SM3_BYTES = SM3_WORDS * 4;           // 115,968 B (2 CTAs/SM)

__global__ __launch_bounds__(256) void k3_out(const float* __restrict__ Q,
                                              const float* __restrict__ Pm,
                                              float* __restrict__ Out) {
    extern __shared__ __align__(16) unsigned smu[];
    unsigned* qp   = smu;                               // stride 72
    unsigned* TQ68 = smu + SM3_QP_W;                    // [64][68]
    float*    OB68 = (float*)TQ68;                      // phase-3 reduce buffer
    unsigned* TP   = smu + SM3_QP_W + SM3_TQ_W;         // [64][68] or [64][72]
    float*    km   = (float*)TP;                        // phase-2 alias
    float*    wmax = (float*)(smu + SM3_QP_W + SM3_TQ_W + SM3_TP_W);
    float*    dq   = wmax + SM3_WMAX;
    float*    dinv = dq + 64;
    float*    vsum_s = dinv + 64;

    int tid = threadIdx.x, lane = tid & 31, warp = tid >> 5;
    int g = lane >> 2, tg = lane & 3;
    int bh = blockIdx.y, n0 = blockIdx.x << 6;
    int rb = (warp & 1) << 5;      // phase-1 n slab
    int cb = (warp >> 1) << 4;     // phase-1 m slab (16 wide)

    float epsp = EPS_F * __expf(fdec(g_kmax_u));   // EPS' = EPS * e^stab

    load_tile_diagS(TQ68, 68, Q + ((size_t)bh * NSEQ + n0) * DDIM, tid, dq);
    for (int i = tid; i < 64; i += 256) vsum_s[i] = g_vsum[bh * 64 + i];

    // ---- phase 1: q_dash -> qp[m][r] raw fp32; row-max in registers ----
    float rmax[2][2] = {{-3.0e38f, -3.0e38f}, {-3.0e38f, -3.0e38f}};
    for (int mc = 0; mc < 5; mc++) {
        int m0 = mc << 6;
        __syncthreads();
        load_tileS(TP, 68, Pm + (size_t)m0 * DDIM, MDIM - m0, tid);
        __syncthreads();

        float c[2][2][4];
#pragma unroll
        for (int i = 0; i < 2; i++)
#pragma unroll
            for (int j = 0; j < 2; j++)
#pragma unroll
                for (int q = 0; q < 4; q++) c[i][j][q] = 0.f;

#pragma unroll
        for (int ks = 0; ks < 8; ks++) {
            int k0 = ks << 3;
            unsigned a[2][4], b[2][2];
#pragma unroll
            for (int i = 0; i < 2; i++) {
                int r0 = rb + (i << 4);
                a[i][0] = TQ68[(r0 + g) * 68 + k0 + tg];
                a[i][1] = TQ68[(r0 + g + 8) * 68 + k0 + tg];
                a[i][2] = TQ68[(r0 + g) * 68 + k0 + tg + 4];
                a[i][3] = TQ68[(r0 + g + 8) * 68 + k0 + tg + 4];
            }
#pragma unroll
            for (int j = 0; j < 2; j++) {
                int mcol = cb + (j << 3) + g;
                b[j][0] = TP[mcol * 68 + k0 + tg];
                b[j][1] = TP[mcol * 68 + k0 + tg + 4];
            }
#pragma unroll
            for (int i = 0; i < 2; i++)
#pragma unroll
                for (int j = 0; j < 2; j++)
                    mma8(c[i][j], a[i][0], a[i][1], a[i][2], a[i][3],
                         b[j][0], b[j][1]);
        }
#pragma unroll
        for (int i = 0; i < 2; i++) {
            int r = rb + (i << 4) + g;
#pragma unroll
            for (int j = 0; j < 2; j++) {
                int m = m0 + cb + (j << 3) + (tg << 1);
                if (m < MPAD) {
                    float v0 = c[i][j][0] * DN_F, v1 = c[i][j][1] * DN_F;
                    float v2 = c[i][j][2] * DN_F, v3 = c[i][j][3] * DN_F;
                    qp[m * 72 + r]           = __float_as_uint(v0);
                    qp[(m + 1) * 72 + r]     = __float_as_uint(v1);
                    qp[m * 72 + r + 8]       = __float_as_uint(v2);
                    qp[(m + 1) * 72 + r + 8] = __float_as_uint(v3);
                    if (m < MDIM) {
                        rmax[i][0] = fmaxf(rmax[i][0], fmaxf(v0, v1));
                        rmax[i][1] = fmaxf(rmax[i][1], fmaxf(v2, v3));
                    }
                }
            }
        }
    }
#pragma unroll
    for (int i = 0; i < 2; i++)
#pragma unroll
        for (int h = 0; h < 2; h++) {
            float v = rmax[i][h];
            v = fmaxf(v, __shfl_xor_sync(0xffffffffu, v, 1));
            v = fmaxf(v, __shfl_xor_sync(0xffffffffu, v, 2));
            if (tg == 0)
                wmax[(warp >> 1) * 64 + rb + (i << 4) + g + (h << 3)] = v;
        }
    for (int i = tid; i < MDIM; i += 256)
        km[i] = g_kmean[bh * MDIM + i] + 4096.0f * epsp;   // KM = ΣE + L*EPS'
    __syncthreads();

    // ---- phase 2: exp + D_inv ----
    {
        int r = tid >> 2, g4 = tid & 3;
        float mx = fmaxf(fmaxf(wmax[r], wmax[64 + r]),
                         fmaxf(wmax[128 + r], wmax[192 + r]));
        float dqr = dq[r];
        float dsum = 0.f;
        for (int cc = g4; cc < MDIM; cc += 4) {
            float val = RATIO_F *
                (__expf(__uint_as_float(qp[cc * 72 + r]) - dqr - mx) + EPS_F);
            qp[cc * 72 + r] = f2tf(val);
            dsum += val * km[cc];
        }
        dsum += __shfl_xor_sync(0xffffffffu, dsum, 1);
        dsum += __shfl_xor_sync(0xffffffffu, dsum, 2);
        if (g4 == 0) dinv[r] = 1.0f / dsum;
    }

    // ---- phase 3: out = (qp @ CTX) * dinv, split-k warp pairs ----
    int sub = warp >> 2;
    int wg  = warp & 3;
    int rb2 = (wg & 1) << 5;
    int eb2 = (wg >> 1) << 5;

    float c[2][4][4];
#pragma unroll
    for (int i = 0; i < 2; i++)
#pragma unroll
        for (int j = 0; j < 4; j++)
#pragma unroll
            for (int q = 0; q < 4; q++) c[i][j][q] = 0.f;

    for (int kc = 0; kc < 5; kc++) {
        int k00 = kc << 6;
        int half = (kc < 4) ? 4 : 1;
        __syncthreads();
        {   // context tile + EPS'*vsum correction
            const float* cbp = g_context + ((size_t)bh * MDIM + k00) * EDIM;
            int valid = MDIM - k00;
#pragma unroll
            for (int t = 0; t < 4; t++) {
                int idx = tid + (t << 8);
                int r = idx >> 4, c4 = (idx & 15) << 2;
                float4 v = make_float4(0.f, 0.f, 0.f, 0.f);
                if (r < valid) {
                    v = *(const float4*)(cbp + (size_t)r * 64 + c4);
                    v.x += epsp * vsum_s[c4];
                    v.y += epsp * vsum_s[c4 + 1];
                    v.z += epsp * vsum_s[c4 + 2];
                    v.w += epsp * vsum_s[c4 + 3];
                }
                uint4 u;
                u.x = f2tf(v.x); u.y = f2tf(v.y);
                u.z = f2tf(v.z); u.w = f2tf(v.w);
                *(uint4*)&TP[r * 72 + c4] = u;
            }
        }
        __syncthreads();

        int ks0 = sub * half, ks1 = ks0 + half;
        for (int ks = ks0; ks < ks1; ks++) {
            int kl = ks << 3;
            unsigned a[2][4], b[4][2];
#pragma unroll
            for (int i = 0; i < 2; i++) {
                int r0 = rb2 + (i << 4);
                a[i][0] = qp[(k00 + kl + tg) * 72 + r0 + g];
                a[i][1] = qp[(k00 + kl + tg) * 72 + r0 + g + 8];
                a[i][2] = qp[(k00 + kl + tg + 4) * 72 + r0 + g];
                a[i][3] = qp[(k00 + kl + tg + 4) * 72 + r0 + g + 8];
            }
#pragma unroll
            for (int j = 0; j < 4; j++) {
                int ec = eb2 + (j << 3) + g;
                b[j][0] = TP[(kl + tg) * 72 + ec];
                b[j][1] = TP[(kl + tg + 4) * 72 + ec];
            }
#pragma unroll
            for (int i = 0; i < 2; i++)
#pragma unroll
                for (int j = 0; j < 4; j++)
                    mma8(c[i][j], a[i][0], a[i][1], a[i][2], a[i][3],
                         b[j][0], b[j][1]);
        }
    }

    __syncthreads();
    if (sub == 0) {
#pragma unroll
        for (int i = 0; i < 2; i++) {
            int row = rb2 + (i << 4) + g;
#pragma unroll
            for (int j = 0; j < 4; j++) {
                int col = eb2 + (j << 3) + (tg << 1);
                OB68[row * 68 + col]           = c[i][j][0];
                OB68[row * 68 + col + 1]       = c[i][j][1];
                OB68[(row + 8) * 68 + col]     = c[i][j][2];
                OB68[(row + 8) * 68 + col + 1] = c[i][j][3];
            }
        }
    }
    __syncthreads();
    if (sub == 1) {
#pragma unroll
        for (int i = 0; i < 2; i++) {
            int row = rb2 + (i << 4) + g;
            float d0 = dinv[row], d1 = dinv[row + 8];
#pragma unroll
            for (int j = 0; j < 4; j++) {
                int col = eb2 + (j << 3) + (tg << 1);
                float2 v0, v1;
                v0.x = (c[i][j][0] + OB68[row * 68 + col])           * d0;
                v0.y = (c[i][j][1] + OB68[row * 68 + col + 1])       * d0;
                v1.x = (c[i][j][2] + OB68[(row + 8) * 68 + col])     * d1;
                v1.y = (c[i][j][3] + OB68[(row + 8) * 68 + col + 1]) * d1;
                *(float2*)(Out + ((size_t)bh * NSEQ + n0 + row) * EDIM + col)     = v0;
                *(float2*)(Out + ((size_t)bh * NSEQ + n0 + row + 8) * EDIM + col) = v1;
            }
        }
    }
}

// ------------------------------ launch -------------------------------------
extern "C" void kernel_launch(void* const* d_in, const int* in_sizes, int n_in,
                              void* d_out, int out_size) {
    const float* q = (const float*)d_in[0];
    const float* k = (const float*)d_in[1];
    const float* v = (const float*)d_in[2];
    const float* P = (const float*)d_in[3];
    float* out = (float*)d_out;

    cudaFuncSetAttribute(kA_context, cudaFuncAttributeMaxDynamicSharedMemorySize,
                         KA_BYTES);
    cudaFuncSetAttribute(k3_out, cudaFuncAttributeMaxDynamicSharedMemorySize,
                         SM3_BYTES);

    k0_init<<<256, 256>>>();
    kA_context<<<dim3(5, BH, 4), 256, KA_BYTES>>>(k, v, P);
    k3_out<<<dim3(NSEQ / 64, BH), 256, SM3_BYTES>>>(q, P, out);
}